// round 3
// baseline (speedup 1.0000x reference)
#include <cuda_runtime.h>
#include <math.h>

#define NN 50000
#define NE_MAX 800000
#define NBLK 196          // ceil(NN/256)
#define EPS_BN 1e-5f
#define SLOPE 0.01f

typedef unsigned long long u64;

// ---------------- scratch (static device memory; no allocs) ----------------
__device__ int   g_degi[NN];
__device__ int   g_scan[NN];
__device__ int   g_bsum[256];
__device__ int   g_start[NN];
__device__ int   g_end[NN];
__device__ int   g_cur[NN];
__device__ int   g_csr[NE_MAX];
__device__ float g_dinv[NN];
__device__ float g_u1[NN * 64];      // x * dinv  (pre-scaled layer-1 messages)
__device__ float g_acc1[NN * 64];
__device__ float g_h1[(size_t)NN * 128];
__device__ float g_u2[NN * 64];
__device__ float g_acc2[NN * 64];
__device__ float g_u3[NN * 64];
// stats layout:
// [0:128) sum1  [128:256) sumsq1  [256:384) scale1  [384:512) shift1
// [512:576) sum2 [576:640) sumsq2 [640:704) scale2  [704:768) shift2(+b2 folded)
__device__ float g_stats[1024];

__device__ __forceinline__ float lrelu(float v) { return v > 0.f ? v : SLOPE * v; }

// packed f32x2 helpers (sm_103a FFMA2 path — not emitted by ptxas from C++)
__device__ __forceinline__ u64 pk2(float v) {
    u64 r; asm("mov.b64 %0, {%1, %1};" : "=l"(r) : "f"(v)); return r;
}
__device__ __forceinline__ void fma2(u64& acc, u64 a, u64 b) {
    asm("fma.rn.f32x2 %0, %1, %2, %0;" : "+l"(acc) : "l"(a), "l"(b));
}
__device__ __forceinline__ void unpk2(u64 v, float& lo, float& hi) {
    asm("mov.b64 {%0, %1}, %2;" : "=f"(lo), "=f"(hi) : "l"(v));
}

// ---------------- CSR build ----------------
__global__ void k_init() {
    int i = blockIdx.x * blockDim.x + threadIdx.x;
    if (i < NN) g_degi[i] = 0;
    if (i < 1024) g_stats[i] = 0.0f;
}

__global__ void k_deg(const int* __restrict__ dst, int nE) {
    int e = blockIdx.x * blockDim.x + threadIdx.x;
    if (e < nE) atomicAdd(&g_degi[dst[e]], 1);
}

__global__ void k_scan1() {
    __shared__ int sh[256];
    int tid = threadIdx.x;
    int i = blockIdx.x * 256 + tid;
    int v = (i < NN) ? g_degi[i] : 0;
    sh[tid] = v;
    __syncthreads();
    #pragma unroll
    for (int off = 1; off < 256; off <<= 1) {
        int t = (tid >= off) ? sh[tid - off] : 0;
        __syncthreads();
        sh[tid] += t;
        __syncthreads();
    }
    if (i < NN) g_scan[i] = sh[tid];          // inclusive within block
    if (tid == 255) g_bsum[blockIdx.x] = sh[255];
}

// fused block-offset reduce + finalize (replaces old scan2+scan3)
__global__ void k_scan3() {
    __shared__ int red[256];
    int tid = threadIdx.x;
    red[tid] = (tid < blockIdx.x) ? g_bsum[tid] : 0;   // NBLK < 256
    __syncthreads();
    #pragma unroll
    for (int off = 128; off > 0; off >>= 1) {
        if (tid < off) red[tid] += red[tid + off];
        __syncthreads();
    }
    int boff = red[0];
    int i = blockIdx.x * 256 + tid;
    if (i >= NN) return;
    int inc = g_scan[i] + boff;
    int deg = g_degi[i];
    g_end[i] = inc;
    g_start[i] = inc - deg;
    g_cur[i] = inc - deg;
}

__global__ void k_fill(const int* __restrict__ src, const int* __restrict__ dst, int nE) {
    int e = blockIdx.x * blockDim.x + threadIdx.x;
    if (e >= nE) return;
    int d = __ldg(&dst[e]);
    int pos = atomicAdd(&g_cur[d], 1);
    g_csr[pos] = __ldg(&src[e]);
}

// dinv + u1 = x*dinv  (self-loop term included implicitly by gather)
__global__ void k_prep(const float* __restrict__ x) {
    int t = blockIdx.x * blockDim.x + threadIdx.x;
    if (t >= NN * 16) return;
    int i = t >> 4;
    float d = rsqrtf((float)(g_degi[i] + 1));   // +1 self loop
    if ((t & 15) == 0) g_dinv[i] = d;
    float4 v = __ldg((const float4*)x + t);
    ((float4*)g_u1)[t] = make_float4(v.x * d, v.y * d, v.z * d, v.w * d);
}

// ---------------- gather (CSR, 16 lanes/node, 4 ch/lane) ----------------
template <int MODE>
__global__ void __launch_bounds__(256) k_gather(float* __restrict__ out,
                                                const float* __restrict__ b3) {
    int t = blockIdx.x * blockDim.x + threadIdx.x;
    if (t >= NN * 16) return;
    int g = t >> 4, lane = t & 15;
    const float* u = (MODE == 1) ? g_u1 : (MODE == 2) ? g_u2 : g_u3;

    float4 acc = __ldg((const float4*)u + t);   // self-loop term
    int j = __ldg(&g_start[g]);
    int end = __ldg(&g_end[g]);
    for (; j + 3 < end; j += 4) {
        int s0 = __ldg(&g_csr[j]);
        int s1 = __ldg(&g_csr[j + 1]);
        int s2 = __ldg(&g_csr[j + 2]);
        int s3 = __ldg(&g_csr[j + 3]);
        float4 v0 = __ldg((const float4*)u + s0 * 16 + lane);
        float4 v1 = __ldg((const float4*)u + s1 * 16 + lane);
        float4 v2 = __ldg((const float4*)u + s2 * 16 + lane);
        float4 v3 = __ldg((const float4*)u + s3 * 16 + lane);
        acc.x += (v0.x + v1.x) + (v2.x + v3.x);
        acc.y += (v0.y + v1.y) + (v2.y + v3.y);
        acc.z += (v0.z + v1.z) + (v2.z + v3.z);
        acc.w += (v0.w + v1.w) + (v2.w + v3.w);
    }
    for (; j < end; j++) {
        int s0 = __ldg(&g_csr[j]);
        float4 v0 = __ldg((const float4*)u + s0 * 16 + lane);
        acc.x += v0.x; acc.y += v0.y; acc.z += v0.z; acc.w += v0.w;
    }

    if (MODE == 1) {
        ((float4*)g_acc1)[t] = acc;
    } else if (MODE == 2) {
        ((float4*)g_acc2)[t] = acc;
    } else {
        float d = g_dinv[g];
        float4 b = __ldg((const float4*)b3 + lane);
        ((float4*)out)[t] = make_float4(fmaf(acc.x, d, b.x), fmaf(acc.y, d, b.y),
                                        fmaf(acc.z, d, b.z), fmaf(acc.w, d, b.w));
    }
}

// ---------------- fused GEMM (packed f32x2 inner loop) ----------------
// MODE 1: in = dinv*acc1 (64) -> W1 -> +b1 -> store h1, BN stats
// MODE 2: in = leaky(h1*scale1+shift1) (128) -> W2 -> *dinv -> store u2
// MODE 3: in = leaky(dinv*acc2*scale2+shift2) (64) -> W3 -> *dinv -> store u3
template <int K, int NC, int RPT, int MODE>
__global__ void __launch_bounds__(256) k_gemm(const float* __restrict__ Wg,
                                              const float* __restrict__ bias) {
    constexpr int R = 16 * RPT;
    constexpr int CPT = NC / 16;
    constexpr int CP2 = CPT / 2;
    constexpr int KQ = K / 4;
    __shared__ float Ws[K * NC];
    __shared__ float Is[R * K];

    const int tid = threadIdx.x;
    const int row0 = blockIdx.x * R;

    {
        const float4* Wg4 = (const float4*)Wg;
        float4* Ws4 = (float4*)Ws;
        #pragma unroll
        for (int i = tid; i < K * NC / 4; i += 256) Ws4[i] = __ldg(Wg4 + i);
    }
    {
        float4* Is4 = (float4*)Is;
        #pragma unroll
        for (int i = tid; i < R * KQ; i += 256) {
            int r = i / KQ, kq = i % KQ;
            int gr = row0 + r;
            float4 v = make_float4(0.f, 0.f, 0.f, 0.f);
            if (gr < NN) {
                if (MODE == 1) {
                    float4 a = __ldg((const float4*)g_acc1 + gr * 16 + kq);
                    float d = __ldg((const float*)&g_dinv[gr]);
                    v = make_float4(a.x * d, a.y * d, a.z * d, a.w * d);
                } else if (MODE == 2) {
                    float4 h = __ldg((const float4*)g_h1 + (size_t)gr * 32 + kq);
                    float4 sc = __ldg((const float4*)(g_stats + 256) + kq);
                    float4 sh = __ldg((const float4*)(g_stats + 384) + kq);
                    v.x = lrelu(fmaf(h.x, sc.x, sh.x));
                    v.y = lrelu(fmaf(h.y, sc.y, sh.y));
                    v.z = lrelu(fmaf(h.z, sc.z, sh.z));
                    v.w = lrelu(fmaf(h.w, sc.w, sh.w));
                } else {
                    float4 a = __ldg((const float4*)g_acc2 + gr * 16 + kq);
                    float d = __ldg((const float*)&g_dinv[gr]);
                    float4 sc = __ldg((const float4*)(g_stats + 640) + kq);
                    float4 sh = __ldg((const float4*)(g_stats + 704) + kq);
                    v.x = lrelu(fmaf(a.x * d, sc.x, sh.x));
                    v.y = lrelu(fmaf(a.y * d, sc.y, sh.y));
                    v.z = lrelu(fmaf(a.z * d, sc.z, sh.z));
                    v.w = lrelu(fmaf(a.w * d, sc.w, sh.w));
                }
            }
            Is4[i] = v;
        }
    }
    __syncthreads();

    const int ct = tid & 15, rt = tid >> 4;
    u64 accp[RPT][CP2];
    #pragma unroll
    for (int j = 0; j < RPT; j++)
        #pragma unroll
        for (int c = 0; c < CP2; c++) accp[j][c] = 0ull;

    const float* isbase = Is + (rt * RPT) * K;
    #pragma unroll 4
    for (int k4 = 0; k4 < K / 4; ++k4) {
        float a[RPT][4];
        #pragma unroll
        for (int j = 0; j < RPT; j++) {
            float4 t4 = *(const float4*)(isbase + j * K + k4 * 4);
            a[j][0] = t4.x; a[j][1] = t4.y; a[j][2] = t4.z; a[j][3] = t4.w;
        }
        #pragma unroll
        for (int kk = 0; kk < 4; kk++) {
            // W row comes packed-for-free from shared: adjacent cols = one u64
            u64 w[CP2];
            const ulonglong2* wr =
                (const ulonglong2*)(Ws + (k4 * 4 + kk) * NC + ct * CPT);
            #pragma unroll
            for (int q = 0; q < CP2 / 2; q++) {
                ulonglong2 w2 = wr[q];
                w[q * 2 + 0] = w2.x; w[q * 2 + 1] = w2.y;
            }
            #pragma unroll
            for (int j = 0; j < RPT; j++) {
                u64 ap = pk2(a[j][kk]);
                #pragma unroll
                for (int c = 0; c < CP2; c++) fma2(accp[j][c], ap, w[c]);
            }
        }
    }

    // unpack accumulators
    float acc[RPT][CPT];
    #pragma unroll
    for (int j = 0; j < RPT; j++)
        #pragma unroll
        for (int c = 0; c < CP2; c++)
            unpk2(accp[j][c], acc[j][2 * c], acc[j][2 * c + 1]);

    if (MODE == 1) {
        float bl[CPT];
        #pragma unroll
        for (int c = 0; c < CPT; c++) bl[c] = __ldg(&bias[ct * CPT + c]);
        #pragma unroll
        for (int j = 0; j < RPT; j++) {
            int gr = row0 + rt * RPT + j;
            if (gr < NN) {
                #pragma unroll
                for (int c = 0; c < CPT; c++) acc[j][c] += bl[c];
                float4* o = (float4*)(g_h1 + (size_t)gr * NC + ct * CPT);
                #pragma unroll
                for (int q = 0; q < CPT / 4; q++)
                    o[q] = make_float4(acc[j][q * 4 + 0], acc[j][q * 4 + 1],
                                       acc[j][q * 4 + 2], acc[j][q * 4 + 3]);
            } else {
                #pragma unroll
                for (int c = 0; c < CPT; c++) acc[j][c] = 0.f;
            }
        }
        __syncthreads();
        float* ssum = Is;
        float* ssq = Is + NC;
        if (tid < 2 * NC) Is[tid] = 0.f;
        __syncthreads();
        #pragma unroll
        for (int c = 0; c < CPT; c++) {
            float sv = 0.f, sq = 0.f;
            #pragma unroll
            for (int j = 0; j < RPT; j++) { sv += acc[j][c]; sq += acc[j][c] * acc[j][c]; }
            atomicAdd(&ssum[ct * CPT + c], sv);
            atomicAdd(&ssq[ct * CPT + c], sq);
        }
        __syncthreads();
        if (tid < NC) {
            atomicAdd(&g_stats[tid], ssum[tid]);
            atomicAdd(&g_stats[128 + tid], ssq[tid]);
        }
    } else {
        float* o0 = (MODE == 2) ? g_u2 : g_u3;
        #pragma unroll
        for (int j = 0; j < RPT; j++) {
            int gr = row0 + rt * RPT + j;
            if (gr >= NN) continue;
            float d = __ldg((const float*)&g_dinv[gr]);
            ((float4*)(o0 + (size_t)gr * NC))[ct] =
                make_float4(acc[j][0] * d, acc[j][1] * d, acc[j][2] * d, acc[j][3] * d);
        }
    }
}

__global__ void k_final1(const float* __restrict__ g1, const float* __restrict__ be1) {
    int c = threadIdx.x;  // 128
    float mean = g_stats[c] * (1.0f / NN);
    float var = g_stats[128 + c] * (1.0f / NN) - mean * mean;
    float sc = rsqrtf(var + EPS_BN) * __ldg(&g1[c]);
    g_stats[256 + c] = sc;
    g_stats[384 + c] = __ldg(&be1[c]) - mean * sc;
}

// stats over h2 = dinv*acc2 + b2
__global__ void k_stats2(const float* __restrict__ b2) {
    __shared__ float ssum[64], ssq[64];
    int tid = threadIdx.x;
    if (tid < 64) ssum[tid] = 0.f;
    else if (tid < 128) ssq[tid - 64] = 0.f;
    __syncthreads();
    int c4 = tid & 15;
    int rs = tid >> 4;
    float4 b = __ldg((const float4*)b2 + c4);
    float4 s = make_float4(0, 0, 0, 0), q = make_float4(0, 0, 0, 0);
    for (int r = blockIdx.x * 16 + rs; r < NN; r += gridDim.x * 16) {
        float d = g_dinv[r];
        float4 a = ((const float4*)g_acc2)[r * 16 + c4];
        float vx = fmaf(a.x, d, b.x), vy = fmaf(a.y, d, b.y);
        float vz = fmaf(a.z, d, b.z), vw = fmaf(a.w, d, b.w);
        s.x += vx; s.y += vy; s.z += vz; s.w += vw;
        q.x += vx * vx; q.y += vy * vy; q.z += vz * vz; q.w += vw * vw;
    }
    atomicAdd(&ssum[c4 * 4 + 0], s.x); atomicAdd(&ssum[c4 * 4 + 1], s.y);
    atomicAdd(&ssum[c4 * 4 + 2], s.z); atomicAdd(&ssum[c4 * 4 + 3], s.w);
    atomicAdd(&ssq[c4 * 4 + 0], q.x);  atomicAdd(&ssq[c4 * 4 + 1], q.y);
    atomicAdd(&ssq[c4 * 4 + 2], q.z);  atomicAdd(&ssq[c4 * 4 + 3], q.w);
    __syncthreads();
    if (tid < 64) {
        atomicAdd(&g_stats[512 + tid], ssum[tid]);
        atomicAdd(&g_stats[576 + tid], ssq[tid]);
    }
}

__global__ void k_final2(const float* __restrict__ g2, const float* __restrict__ be2,
                         const float* __restrict__ b2) {
    int c = threadIdx.x;  // 64
    float mean = g_stats[512 + c] * (1.0f / NN);
    float var = g_stats[576 + c] * (1.0f / NN) - mean * mean;
    float sc = rsqrtf(var + EPS_BN) * __ldg(&g2[c]);
    g_stats[640 + c] = sc;
    g_stats[704 + c] = __ldg(&be2[c]) + (__ldg(&b2[c]) - mean) * sc;
}

// ---------------- launcher ----------------
extern "C" void kernel_launch(void* const* d_in, const int* in_sizes, int n_in,
                              void* d_out, int out_size) {
    const float* x  = (const float*)d_in[0];
    const int* ei   = (const int*)d_in[1];
    const float* W1 = (const float*)d_in[2];
    const float* b1 = (const float*)d_in[3];
    const float* g1 = (const float*)d_in[4];
    const float* be1= (const float*)d_in[5];
    const float* W2 = (const float*)d_in[6];
    const float* b2 = (const float*)d_in[7];
    const float* g2 = (const float*)d_in[8];
    const float* be2= (const float*)d_in[9];
    const float* W3 = (const float*)d_in[10];
    const float* b3 = (const float*)d_in[11];

    const int nE = in_sizes[1] / 2;
    const int* src = ei;
    const int* dst = ei + nE;

    // CSR build
    k_init<<<(NN + 255) / 256, 256>>>();
    k_deg<<<(nE + 255) / 256, 256>>>(dst, nE);
    k_scan1<<<NBLK, 256>>>();
    k_scan3<<<NBLK, 256>>>();
    k_fill<<<(nE + 255) / 256, 256>>>(src, dst, nE);
    k_prep<<<(NN * 16 + 255) / 256, 256>>>(x);

    // layer 1 (aggregate at 64 ch BEFORE GEMM: A(xW) == (Ax)W)
    k_gather<1><<<(NN * 16 + 255) / 256, 256>>>(nullptr, nullptr);
    k_gemm<64, 128, 4, 1><<<(NN + 63) / 64, 256>>>(W1, b1);
    k_final1<<<1, 128>>>(g1, be1);

    // layer 2
    k_gemm<128, 64, 2, 2><<<(NN + 31) / 32, 256>>>(W2, nullptr);
    k_gather<2><<<(NN * 16 + 255) / 256, 256>>>(nullptr, nullptr);
    k_stats2<<<256, 256>>>(b2);
    k_final2<<<1, 64>>>(g2, be2, b2);

    // layer 3
    k_gemm<64, 64, 4, 3><<<(NN + 63) / 64, 256>>>(W3, nullptr);
    k_gather<3><<<(NN * 16 + 255) / 256, 256>>>((float*)d_out, b3);
}

// round 4
// speedup vs baseline: 1.0347x; 1.0347x over previous
#include <cuda_runtime.h>
#include <cuda_fp16.h>
#include <math.h>

#define NN 50000
#define NE_MAX 800000
#define NBLK 196          // ceil(NN/256)
#define EPS_BN 1e-5f
#define SLOPE 0.01f

// ---------------- scratch (static device memory; no allocs) ----------------
__device__ int   g_degi[NN];
__device__ int   g_scan[NN];
__device__ int   g_bsum[256];
__device__ int   g_start[NN];
__device__ int   g_end[NN];
__device__ int   g_cur[NN];
__device__ int   g_csr[NE_MAX];
__device__ float g_dinv[NN];
// fp16 message buffers: 64 ch = 16 uint2 (4 ch per uint2 as 2x half2)
__device__ uint2 g_u1[NN * 16];
__device__ uint2 g_u2[NN * 16];
__device__ uint2 g_u3[NN * 16];
__device__ float g_acc1[NN * 64];
__device__ float g_h1[(size_t)NN * 128];
__device__ float g_acc2[NN * 64];
// stats layout:
// [0:128) sum1  [128:256) sumsq1  [256:384) scale1  [384:512) shift1
// [512:576) sum2 [576:640) sumsq2 [640:704) scale2  [704:768) shift2(+b2 folded)
__device__ float g_stats[1024];

__device__ __forceinline__ float lrelu(float v) { return v > 0.f ? v : SLOPE * v; }

__device__ __forceinline__ unsigned pack_h2(float a, float b) {
    __half2 h = __floats2half2_rn(a, b);
    return *(unsigned*)&h;
}
__device__ __forceinline__ float2 unpack_h2(unsigned v) {
    __half2 h = *(__half2*)&v;
    return __half22float2(h);
}

// ---------------- CSR build ----------------
__global__ void k_init() {
    int i = blockIdx.x * blockDim.x + threadIdx.x;
    if (i < NN) g_degi[i] = 0;
    if (i < 1024) g_stats[i] = 0.0f;
}

__global__ void k_deg(const int* __restrict__ dst, int nE) {
    int e = blockIdx.x * blockDim.x + threadIdx.x;
    if (e < nE) atomicAdd(&g_degi[dst[e]], 1);
}

__global__ void k_scan1() {
    __shared__ int sh[256];
    int tid = threadIdx.x;
    int i = blockIdx.x * 256 + tid;
    int v = (i < NN) ? g_degi[i] : 0;
    sh[tid] = v;
    __syncthreads();
    #pragma unroll
    for (int off = 1; off < 256; off <<= 1) {
        int t = (tid >= off) ? sh[tid - off] : 0;
        __syncthreads();
        sh[tid] += t;
        __syncthreads();
    }
    if (i < NN) g_scan[i] = sh[tid];          // inclusive within block
    if (tid == 255) g_bsum[blockIdx.x] = sh[255];
}

// fused block-offset reduce + finalize
__global__ void k_scan3() {
    __shared__ int red[256];
    int tid = threadIdx.x;
    red[tid] = (tid < blockIdx.x) ? g_bsum[tid] : 0;   // NBLK < 256
    __syncthreads();
    #pragma unroll
    for (int off = 128; off > 0; off >>= 1) {
        if (tid < off) red[tid] += red[tid + off];
        __syncthreads();
    }
    int boff = red[0];
    int i = blockIdx.x * 256 + tid;
    if (i >= NN) return;
    int inc = g_scan[i] + boff;
    int deg = g_degi[i];
    g_end[i] = inc;
    g_start[i] = inc - deg;
    g_cur[i] = inc - deg;
}

__global__ void k_fill(const int* __restrict__ src, const int* __restrict__ dst, int nE) {
    int e = blockIdx.x * blockDim.x + threadIdx.x;
    if (e >= nE) return;
    int d = __ldg(&dst[e]);
    int pos = atomicAdd(&g_cur[d], 1);
    g_csr[pos] = __ldg(&src[e]);
}

// dinv + u1 = fp16(x*dinv)
__global__ void k_prep(const float* __restrict__ x) {
    int t = blockIdx.x * blockDim.x + threadIdx.x;
    if (t >= NN * 16) return;
    int i = t >> 4;
    float d = rsqrtf((float)(g_degi[i] + 1));   // +1 self loop
    if ((t & 15) == 0) g_dinv[i] = d;
    float4 v = __ldg((const float4*)x + t);
    g_u1[t] = make_uint2(pack_h2(v.x * d, v.y * d), pack_h2(v.z * d, v.w * d));
}

// ---------------- gather (CSR, 16 lanes/node, 4 ch/lane, fp16 msgs) ----------------
template <int MODE>
__global__ void __launch_bounds__(256) k_gather(float* __restrict__ out,
                                                const float* __restrict__ b3) {
    int t = blockIdx.x * blockDim.x + threadIdx.x;
    if (t >= NN * 16) return;
    int g = t >> 4, lane = t & 15;
    const uint2* u = (MODE == 1) ? g_u1 : (MODE == 2) ? g_u2 : g_u3;

    float4 acc;
    {   // self-loop term
        uint2 r = __ldg(u + t);
        float2 a = unpack_h2(r.x), b = unpack_h2(r.y);
        acc = make_float4(a.x, a.y, b.x, b.y);
    }
    int j = __ldg(&g_start[g]);
    int end = __ldg(&g_end[g]);
    for (; j + 3 < end; j += 4) {
        int s0 = __ldg(&g_csr[j]);
        int s1 = __ldg(&g_csr[j + 1]);
        int s2 = __ldg(&g_csr[j + 2]);
        int s3 = __ldg(&g_csr[j + 3]);
        uint2 r0 = __ldg(u + s0 * 16 + lane);
        uint2 r1 = __ldg(u + s1 * 16 + lane);
        uint2 r2 = __ldg(u + s2 * 16 + lane);
        uint2 r3 = __ldg(u + s3 * 16 + lane);
        float2 a0 = unpack_h2(r0.x), b0 = unpack_h2(r0.y);
        float2 a1 = unpack_h2(r1.x), b1 = unpack_h2(r1.y);
        float2 a2 = unpack_h2(r2.x), b2 = unpack_h2(r2.y);
        float2 a3 = unpack_h2(r3.x), b3v = unpack_h2(r3.y);
        acc.x += (a0.x + a1.x) + (a2.x + a3.x);
        acc.y += (a0.y + a1.y) + (a2.y + a3.y);
        acc.z += (b0.x + b1.x) + (b2.x + b3v.x);
        acc.w += (b0.y + b1.y) + (b2.y + b3v.y);
    }
    for (; j < end; j++) {
        int s0 = __ldg(&g_csr[j]);
        uint2 r0 = __ldg(u + s0 * 16 + lane);
        float2 a0 = unpack_h2(r0.x), b0 = unpack_h2(r0.y);
        acc.x += a0.x; acc.y += a0.y; acc.z += b0.x; acc.w += b0.y;
    }

    if (MODE == 1) {
        ((float4*)g_acc1)[t] = acc;
    } else if (MODE == 2) {
        ((float4*)g_acc2)[t] = acc;
    } else {
        float d = g_dinv[g];
        float4 b = __ldg((const float4*)b3 + lane);
        ((float4*)out)[t] = make_float4(fmaf(acc.x, d, b.x), fmaf(acc.y, d, b.y),
                                        fmaf(acc.z, d, b.z), fmaf(acc.w, d, b.w));
    }
}

// ---------------- fused GEMM (scalar FFMA inner loop — round-2 proven) ----------------
// MODE 1: in = dinv*acc1 (64) -> W1 -> +b1 -> store h1, BN stats
// MODE 2: in = leaky(h1*scale1+shift1) (128) -> W2 -> *dinv -> store u2 (fp16)
// MODE 3: in = leaky(dinv*acc2*scale2+shift2) (64) -> W3 -> *dinv -> store u3 (fp16)
template <int K, int NC, int RPT, int MODE>
__global__ void __launch_bounds__(256) k_gemm(const float* __restrict__ Wg,
                                              const float* __restrict__ bias) {
    constexpr int R = 16 * RPT;
    constexpr int CPT = NC / 16;
    constexpr int KQ = K / 4;
    __shared__ float Ws[K * NC];
    __shared__ float Is[R * K];

    const int tid = threadIdx.x;
    const int row0 = blockIdx.x * R;

    {
        const float4* Wg4 = (const float4*)Wg;
        float4* Ws4 = (float4*)Ws;
        #pragma unroll
        for (int i = tid; i < K * NC / 4; i += 256) Ws4[i] = __ldg(Wg4 + i);
    }
    {
        float4* Is4 = (float4*)Is;
        #pragma unroll
        for (int i = tid; i < R * KQ; i += 256) {
            int r = i / KQ, kq = i % KQ;
            int gr = row0 + r;
            float4 v = make_float4(0.f, 0.f, 0.f, 0.f);
            if (gr < NN) {
                if (MODE == 1) {
                    float4 a = __ldg((const float4*)g_acc1 + gr * 16 + kq);
                    float d = __ldg((const float*)&g_dinv[gr]);
                    v = make_float4(a.x * d, a.y * d, a.z * d, a.w * d);
                } else if (MODE == 2) {
                    float4 h = __ldg((const float4*)g_h1 + (size_t)gr * 32 + kq);
                    float4 sc = __ldg((const float4*)(g_stats + 256) + kq);
                    float4 sh = __ldg((const float4*)(g_stats + 384) + kq);
                    v.x = lrelu(fmaf(h.x, sc.x, sh.x));
                    v.y = lrelu(fmaf(h.y, sc.y, sh.y));
                    v.z = lrelu(fmaf(h.z, sc.z, sh.z));
                    v.w = lrelu(fmaf(h.w, sc.w, sh.w));
                } else {
                    float4 a = __ldg((const float4*)g_acc2 + gr * 16 + kq);
                    float d = __ldg((const float*)&g_dinv[gr]);
                    float4 sc = __ldg((const float4*)(g_stats + 640) + kq);
                    float4 sh = __ldg((const float4*)(g_stats + 704) + kq);
                    v.x = lrelu(fmaf(a.x * d, sc.x, sh.x));
                    v.y = lrelu(fmaf(a.y * d, sc.y, sh.y));
                    v.z = lrelu(fmaf(a.z * d, sc.z, sh.z));
                    v.w = lrelu(fmaf(a.w * d, sc.w, sh.w));
                }
            }
            Is4[i] = v;
        }
    }
    __syncthreads();

    const int ct = tid & 15, rt = tid >> 4;
    float acc[RPT][CPT];
    #pragma unroll
    for (int j = 0; j < RPT; j++)
        #pragma unroll
        for (int c = 0; c < CPT; c++) acc[j][c] = 0.f;

    const float* isbase = Is + (rt * RPT) * K;
    #pragma unroll 4
    for (int k4 = 0; k4 < K / 4; ++k4) {
        float a[RPT][4];
        #pragma unroll
        for (int j = 0; j < RPT; j++) {
            float4 t4 = *(const float4*)(isbase + j * K + k4 * 4);
            a[j][0] = t4.x; a[j][1] = t4.y; a[j][2] = t4.z; a[j][3] = t4.w;
        }
        #pragma unroll
        for (int kk = 0; kk < 4; kk++) {
            float w[CPT];
            const float4* wr = (const float4*)(Ws + (k4 * 4 + kk) * NC + ct * CPT);
            #pragma unroll
            for (int q = 0; q < CPT / 4; q++) {
                float4 w4 = wr[q];
                w[q * 4 + 0] = w4.x; w[q * 4 + 1] = w4.y;
                w[q * 4 + 2] = w4.z; w[q * 4 + 3] = w4.w;
            }
            #pragma unroll
            for (int j = 0; j < RPT; j++)
                #pragma unroll
                for (int c = 0; c < CPT; c++)
                    acc[j][c] = fmaf(a[j][kk], w[c], acc[j][c]);
        }
    }

    if (MODE == 1) {
        float bl[CPT];
        #pragma unroll
        for (int c = 0; c < CPT; c++) bl[c] = __ldg(&bias[ct * CPT + c]);
        #pragma unroll
        for (int j = 0; j < RPT; j++) {
            int gr = row0 + rt * RPT + j;
            if (gr < NN) {
                #pragma unroll
                for (int c = 0; c < CPT; c++) acc[j][c] += bl[c];
                float4* o = (float4*)(g_h1 + (size_t)gr * NC + ct * CPT);
                #pragma unroll
                for (int q = 0; q < CPT / 4; q++)
                    o[q] = make_float4(acc[j][q * 4 + 0], acc[j][q * 4 + 1],
                                       acc[j][q * 4 + 2], acc[j][q * 4 + 3]);
            } else {
                #pragma unroll
                for (int c = 0; c < CPT; c++) acc[j][c] = 0.f;
            }
        }
        __syncthreads();
        float* ssum = Is;
        float* ssq = Is + NC;
        if (tid < 2 * NC) Is[tid] = 0.f;
        __syncthreads();
        #pragma unroll
        for (int c = 0; c < CPT; c++) {
            float sv = 0.f, sq = 0.f;
            #pragma unroll
            for (int j = 0; j < RPT; j++) { sv += acc[j][c]; sq += acc[j][c] * acc[j][c]; }
            atomicAdd(&ssum[ct * CPT + c], sv);
            atomicAdd(&ssq[ct * CPT + c], sq);
        }
        __syncthreads();
        if (tid < NC) {
            atomicAdd(&g_stats[tid], ssum[tid]);
            atomicAdd(&g_stats[128 + tid], ssq[tid]);
        }
    } else {
        uint2* o0 = (MODE == 2) ? g_u2 : g_u3;
        #pragma unroll
        for (int j = 0; j < RPT; j++) {
            int gr = row0 + rt * RPT + j;
            if (gr >= NN) continue;
            float d = __ldg((const float*)&g_dinv[gr]);
            o0[gr * 16 + ct] = make_uint2(pack_h2(acc[j][0] * d, acc[j][1] * d),
                                          pack_h2(acc[j][2] * d, acc[j][3] * d));
        }
    }
}

__global__ void k_final1(const float* __restrict__ g1, const float* __restrict__ be1) {
    int c = threadIdx.x;  // 128
    float mean = g_stats[c] * (1.0f / NN);
    float var = g_stats[128 + c] * (1.0f / NN) - mean * mean;
    float sc = rsqrtf(var + EPS_BN) * __ldg(&g1[c]);
    g_stats[256 + c] = sc;
    g_stats[384 + c] = __ldg(&be1[c]) - mean * sc;
}

// stats over h2 = dinv*acc2 + b2
__global__ void k_stats2(const float* __restrict__ b2) {
    __shared__ float ssum[64], ssq[64];
    int tid = threadIdx.x;
    if (tid < 64) ssum[tid] = 0.f;
    else if (tid < 128) ssq[tid - 64] = 0.f;
    __syncthreads();
    int c4 = tid & 15;
    int rs = tid >> 4;
    float4 b = __ldg((const float4*)b2 + c4);
    float4 s = make_float4(0, 0, 0, 0), q = make_float4(0, 0, 0, 0);
    for (int r = blockIdx.x * 16 + rs; r < NN; r += gridDim.x * 16) {
        float d = g_dinv[r];
        float4 a = ((const float4*)g_acc2)[r * 16 + c4];
        float vx = fmaf(a.x, d, b.x), vy = fmaf(a.y, d, b.y);
        float vz = fmaf(a.z, d, b.z), vw = fmaf(a.w, d, b.w);
        s.x += vx; s.y += vy; s.z += vz; s.w += vw;
        q.x += vx * vx; q.y += vy * vy; q.z += vz * vz; q.w += vw * vw;
    }
    atomicAdd(&ssum[c4 * 4 + 0], s.x); atomicAdd(&ssum[c4 * 4 + 1], s.y);
    atomicAdd(&ssum[c4 * 4 + 2], s.z); atomicAdd(&ssum[c4 * 4 + 3], s.w);
    atomicAdd(&ssq[c4 * 4 + 0], q.x);  atomicAdd(&ssq[c4 * 4 + 1], q.y);
    atomicAdd(&ssq[c4 * 4 + 2], q.z);  atomicAdd(&ssq[c4 * 4 + 3], q.w);
    __syncthreads();
    if (tid < 64) {
        atomicAdd(&g_stats[512 + tid], ssum[tid]);
        atomicAdd(&g_stats[576 + tid], ssq[tid]);
    }
}

__global__ void k_final2(const float* __restrict__ g2, const float* __restrict__ be2,
                         const float* __restrict__ b2) {
    int c = threadIdx.x;  // 64
    float mean = g_stats[512 + c] * (1.0f / NN);
    float var = g_stats[576 + c] * (1.0f / NN) - mean * mean;
    float sc = rsqrtf(var + EPS_BN) * __ldg(&g2[c]);
    g_stats[640 + c] = sc;
    g_stats[704 + c] = __ldg(&be2[c]) + (__ldg(&b2[c]) - mean) * sc;
}

// ---------------- launcher ----------------
extern "C" void kernel_launch(void* const* d_in, const int* in_sizes, int n_in,
                              void* d_out, int out_size) {
    const float* x  = (const float*)d_in[0];
    const int* ei   = (const int*)d_in[1];
    const float* W1 = (const float*)d_in[2];
    const float* b1 = (const float*)d_in[3];
    const float* g1 = (const float*)d_in[4];
    const float* be1= (const float*)d_in[5];
    const float* W2 = (const float*)d_in[6];
    const float* b2 = (const float*)d_in[7];
    const float* g2 = (const float*)d_in[8];
    const float* be2= (const float*)d_in[9];
    const float* W3 = (const float*)d_in[10];
    const float* b3 = (const float*)d_in[11];

    const int nE = in_sizes[1] / 2;
    const int* src = ei;
    const int* dst = ei + nE;

    // CSR build
    k_init<<<(NN + 255) / 256, 256>>>();
    k_deg<<<(nE + 255) / 256, 256>>>(dst, nE);
    k_scan1<<<NBLK, 256>>>();
    k_scan3<<<NBLK, 256>>>();
    k_fill<<<(nE + 255) / 256, 256>>>(src, dst, nE);
    k_prep<<<(NN * 16 + 255) / 256, 256>>>(x);

    // layer 1 (aggregate at 64 ch BEFORE GEMM: A(xW) == (Ax)W)
    k_gather<1><<<(NN * 16 + 255) / 256, 256>>>(nullptr, nullptr);
    k_gemm<64, 128, 4, 1><<<(NN + 63) / 64, 256>>>(W1, b1);
    k_final1<<<1, 128>>>(g1, be1);

    // layer 2
    k_gemm<128, 64, 2, 2><<<(NN + 31) / 32, 256>>>(W2, nullptr);
    k_gather<2><<<(NN * 16 + 255) / 256, 256>>>(nullptr, nullptr);
    k_stats2<<<256, 256>>>(b2);
    k_final2<<<1, 64>>>(g2, be2, b2);

    // layer 3
    k_gemm<64, 64, 4, 3><<<(NN + 63) / 64, 256>>>(W3, nullptr);
    k_gather<3><<<(NN * 16 + 255) / 256, 256>>>((float*)d_out, b3);
}

// round 5
// speedup vs baseline: 1.0529x; 1.0176x over previous
#include <cuda_runtime.h>
#include <cuda_fp16.h>
#include <math.h>

#define NN 50000
#define NE_MAX 800000
#define NBLK 196          // ceil(NN/256)
#define EPS_BN 1e-5f
#define SLOPE 0.01f

// ---------------- scratch (static device memory; no allocs) ----------------
__device__ int   g_degi[NN];
__device__ int   g_counter;
__device__ int   g_start[NN];
__device__ int   g_end[NN];
__device__ int   g_cur[NN];
__device__ int   g_csr[NE_MAX];
__device__ float g_dinv[NN];
// fp16 message buffers: 64 ch = 16 uint2 (4 ch per uint2 as 2x half2)
__device__ uint2 g_u1[NN * 16];
__device__ uint2 g_u2[NN * 16];
__device__ uint2 g_u3[NN * 16];
__device__ float g_acc1[NN * 64];
__device__ float g_h1[(size_t)NN * 128];
__device__ float g_acc2[NN * 64];
// stats layout:
// [0:128) sum1  [128:256) sumsq1  [256:384) scale1  [384:512) shift1
// [512:576) sum2 [576:640) sumsq2
__device__ float g_stats[1024];

__device__ __forceinline__ float lrelu(float v) { return v > 0.f ? v : SLOPE * v; }

__device__ __forceinline__ unsigned pack_h2(float a, float b) {
    __half2 h = __floats2half2_rn(a, b);
    return *(unsigned*)&h;
}
__device__ __forceinline__ float2 unpack_h2(unsigned v) {
    __half2 h = *(__half2*)&v;
    return __half22float2(h);
}

// ---------------- CSR build ----------------
__global__ void k_init() {
    int i = blockIdx.x * blockDim.x + threadIdx.x;
    if (i < NN) g_degi[i] = 0;
    if (i < 1024) g_stats[i] = 0.0f;
    if (i == 0) g_counter = 0;
}

__global__ void k_deg(const int* __restrict__ dst, int nE) {
    int e = blockIdx.x * blockDim.x + threadIdx.x;
    if (e < nE) atomicAdd(&g_degi[dst[e]], 1);
}

// single-kernel CSR ranges (ticket-counter scan; region order irrelevant)
// + fused prep: dinv + u1 = fp16(x * dinv)
__global__ void __launch_bounds__(256) k_scanprep(const float* __restrict__ x) {
    __shared__ int sh[256];
    __shared__ float sdinv[256];
    __shared__ int sbase;
    int tid = threadIdx.x;
    int i = blockIdx.x * 256 + tid;
    int deg = (i < NN) ? g_degi[i] : 0;
    sh[tid] = deg;
    __syncthreads();
    #pragma unroll
    for (int off = 1; off < 256; off <<= 1) {
        int t = (tid >= off) ? sh[tid - off] : 0;
        __syncthreads();
        sh[tid] += t;
        __syncthreads();
    }
    if (tid == 255) sbase = atomicAdd(&g_counter, sh[255]);
    float d = rsqrtf((float)(deg + 1));      // +1 self loop
    sdinv[tid] = d;
    __syncthreads();
    if (i < NN) {
        int end = sbase + sh[tid];
        g_end[i] = end;
        g_start[i] = end - deg;
        g_cur[i] = end - deg;
        g_dinv[i] = d;
    }
    // u1 staging: 16 float4-quads per node
    int base = blockIdx.x * 4096;
    #pragma unroll
    for (int q = 0; q < 16; q++) {
        int idx = base + q * 256 + tid;
        if (idx < NN * 16) {
            float dd = sdinv[(idx >> 4) - blockIdx.x * 256];
            float4 v = __ldg((const float4*)x + idx);
            g_u1[idx] = make_uint2(pack_h2(v.x * dd, v.y * dd),
                                   pack_h2(v.z * dd, v.w * dd));
        }
    }
}

__global__ void k_fill(const int* __restrict__ src, const int* __restrict__ dst, int nE) {
    int e = blockIdx.x * blockDim.x + threadIdx.x;
    if (e >= nE) return;
    int d = __ldg(&dst[e]);
    int pos = atomicAdd(&g_cur[d], 1);
    g_csr[pos] = __ldg(&src[e]);
}

// ---------------- gather (CSR, 16 lanes/node, 4 ch/lane, fp16 msgs) ----------------
// MODE 2 additionally accumulates BN stats of h2 = dinv*acc2 + b2 into g_stats[512..]
// NOTE: grid is exactly NN*16/256 = 3125 blocks (no partial block; no divergent exits)
template <int MODE>
__global__ void __launch_bounds__(256) k_gather(float* __restrict__ out,
                                                const float* __restrict__ bp) {
    __shared__ float ssum[64];
    __shared__ float ssq[64];
    int tid = threadIdx.x;
    if (MODE == 2) {
        if (tid < 64) ssum[tid] = 0.f;
        else if (tid < 128) ssq[tid - 64] = 0.f;
        __syncthreads();
    }
    int t = blockIdx.x * blockDim.x + tid;
    int g = t >> 4, lane = t & 15;
    const uint2* u = (MODE == 1) ? g_u1 : (MODE == 2) ? g_u2 : g_u3;

    float4 acc;
    {   // self-loop term
        uint2 r = __ldg(u + t);
        float2 a = unpack_h2(r.x), b = unpack_h2(r.y);
        acc = make_float4(a.x, a.y, b.x, b.y);
    }
    int j = __ldg(&g_start[g]);
    int end = __ldg(&g_end[g]);
    for (; j + 3 < end; j += 4) {
        int s0 = __ldg(&g_csr[j]);
        int s1 = __ldg(&g_csr[j + 1]);
        int s2 = __ldg(&g_csr[j + 2]);
        int s3 = __ldg(&g_csr[j + 3]);
        uint2 r0 = __ldg(u + s0 * 16 + lane);
        uint2 r1 = __ldg(u + s1 * 16 + lane);
        uint2 r2 = __ldg(u + s2 * 16 + lane);
        uint2 r3 = __ldg(u + s3 * 16 + lane);
        float2 a0 = unpack_h2(r0.x), b0 = unpack_h2(r0.y);
        float2 a1 = unpack_h2(r1.x), b1 = unpack_h2(r1.y);
        float2 a2 = unpack_h2(r2.x), b2v = unpack_h2(r2.y);
        float2 a3 = unpack_h2(r3.x), b3v = unpack_h2(r3.y);
        acc.x += (a0.x + a1.x) + (a2.x + a3.x);
        acc.y += (a0.y + a1.y) + (a2.y + a3.y);
        acc.z += (b0.x + b1.x) + (b2v.x + b3v.x);
        acc.w += (b0.y + b1.y) + (b2v.y + b3v.y);
    }
    for (; j < end; j++) {
        int s0 = __ldg(&g_csr[j]);
        uint2 r0 = __ldg(u + s0 * 16 + lane);
        float2 a0 = unpack_h2(r0.x), b0 = unpack_h2(r0.y);
        acc.x += a0.x; acc.y += a0.y; acc.z += b0.x; acc.w += b0.y;
    }

    if (MODE == 1) {
        ((float4*)g_acc1)[t] = acc;
    } else if (MODE == 2) {
        ((float4*)g_acc2)[t] = acc;
        // fused BN stats of h2 = dinv*acc + b2
        float d = g_dinv[g];
        float4 b = __ldg((const float4*)bp + lane);
        float v0 = fmaf(acc.x, d, b.x), v1 = fmaf(acc.y, d, b.y);
        float v2 = fmaf(acc.z, d, b.z), v3 = fmaf(acc.w, d, b.w);
        float q0 = v0 * v0, q1 = v1 * v1, q2 = v2 * v2, q3 = v3 * v3;
        v0 += __shfl_xor_sync(0xffffffffu, v0, 16);
        v1 += __shfl_xor_sync(0xffffffffu, v1, 16);
        v2 += __shfl_xor_sync(0xffffffffu, v2, 16);
        v3 += __shfl_xor_sync(0xffffffffu, v3, 16);
        q0 += __shfl_xor_sync(0xffffffffu, q0, 16);
        q1 += __shfl_xor_sync(0xffffffffu, q1, 16);
        q2 += __shfl_xor_sync(0xffffffffu, q2, 16);
        q3 += __shfl_xor_sync(0xffffffffu, q3, 16);
        if ((tid & 31) < 16) {
            atomicAdd(&ssum[lane * 4 + 0], v0);
            atomicAdd(&ssum[lane * 4 + 1], v1);
            atomicAdd(&ssum[lane * 4 + 2], v2);
            atomicAdd(&ssum[lane * 4 + 3], v3);
            atomicAdd(&ssq[lane * 4 + 0], q0);
            atomicAdd(&ssq[lane * 4 + 1], q1);
            atomicAdd(&ssq[lane * 4 + 2], q2);
            atomicAdd(&ssq[lane * 4 + 3], q3);
        }
        __syncthreads();
        if (tid < 64) {
            atomicAdd(&g_stats[512 + tid], ssum[tid]);
            atomicAdd(&g_stats[576 + tid], ssq[tid]);
        }
    } else {
        float d = g_dinv[g];
        float4 b = __ldg((const float4*)bp + lane);
        ((float4*)out)[t] = make_float4(fmaf(acc.x, d, b.x), fmaf(acc.y, d, b.y),
                                        fmaf(acc.z, d, b.z), fmaf(acc.w, d, b.w));
    }
}

// ---------------- fused GEMM ----------------
// MODE 1: in = dinv*acc1 (64) -> W1 -> +b1 -> store h1, BN stats (p0 = b1)
// MODE 2: in = leaky(h1*scale1+shift1) (128) -> W2 -> *dinv -> u2 fp16 (scale/shift from g_stats)
// MODE 3: in = leaky((dinv*acc2)*sc2+sh2) (64) -> W3 -> *dinv -> u3 fp16
//         (inline final2: p0=g2, p1=be2, p2=b2)
template <int K, int NC, int RPT, int MODE>
__global__ void __launch_bounds__(256) k_gemm(const float* __restrict__ Wg,
                                              const float* __restrict__ p0,
                                              const float* __restrict__ p1,
                                              const float* __restrict__ p2) {
    constexpr int R = 16 * RPT;
    constexpr int CPT = NC / 16;
    constexpr int KQ = K / 4;
    __shared__ float Ws[K * NC];
    __shared__ float Is[R * K];
    __shared__ float s_sc[MODE == 3 ? 64 : 1];
    __shared__ float s_sh[MODE == 3 ? 64 : 1];

    const int tid = threadIdx.x;
    const int row0 = blockIdx.x * R;

    if (MODE == 3) {
        if (tid < 64) {
            float mean = g_stats[512 + tid] * (1.0f / NN);
            float var = g_stats[576 + tid] * (1.0f / NN) - mean * mean;
            float sc = rsqrtf(var + EPS_BN) * __ldg(&p0[tid]);
            s_sc[tid] = sc;
            s_sh[tid] = __ldg(&p1[tid]) + (__ldg(&p2[tid]) - mean) * sc;
        }
        __syncthreads();
    }

    {
        const float4* Wg4 = (const float4*)Wg;
        float4* Ws4 = (float4*)Ws;
        #pragma unroll
        for (int i = tid; i < K * NC / 4; i += 256) Ws4[i] = __ldg(Wg4 + i);
    }
    {
        float4* Is4 = (float4*)Is;
        #pragma unroll
        for (int i = tid; i < R * KQ; i += 256) {
            int r = i / KQ, kq = i % KQ;
            int gr = row0 + r;
            float4 v = make_float4(0.f, 0.f, 0.f, 0.f);
            if (gr < NN) {
                if (MODE == 1) {
                    float4 a = __ldg((const float4*)g_acc1 + gr * 16 + kq);
                    float d = __ldg((const float*)&g_dinv[gr]);
                    v = make_float4(a.x * d, a.y * d, a.z * d, a.w * d);
                } else if (MODE == 2) {
                    float4 h = __ldg((const float4*)g_h1 + (size_t)gr * 32 + kq);
                    float4 sc = __ldg((const float4*)(g_stats + 256) + kq);
                    float4 sh = __ldg((const float4*)(g_stats + 384) + kq);
                    v.x = lrelu(fmaf(h.x, sc.x, sh.x));
                    v.y = lrelu(fmaf(h.y, sc.y, sh.y));
                    v.z = lrelu(fmaf(h.z, sc.z, sh.z));
                    v.w = lrelu(fmaf(h.w, sc.w, sh.w));
                } else {
                    float4 a = __ldg((const float4*)g_acc2 + gr * 16 + kq);
                    float d = __ldg((const float*)&g_dinv[gr]);
                    float4 sc = *(const float4*)(s_sc + kq * 4);
                    float4 sh = *(const float4*)(s_sh + kq * 4);
                    v.x = lrelu(fmaf(a.x * d, sc.x, sh.x));
                    v.y = lrelu(fmaf(a.y * d, sc.y, sh.y));
                    v.z = lrelu(fmaf(a.z * d, sc.z, sh.z));
                    v.w = lrelu(fmaf(a.w * d, sc.w, sh.w));
                }
            }
            Is4[i] = v;
        }
    }
    __syncthreads();

    const int ct = tid & 15, rt = tid >> 4;
    float acc[RPT][CPT];
    #pragma unroll
    for (int j = 0; j < RPT; j++)
        #pragma unroll
        for (int c = 0; c < CPT; c++) acc[j][c] = 0.f;

    const float* isbase = Is + (rt * RPT) * K;
    #pragma unroll 4
    for (int k4 = 0; k4 < K / 4; ++k4) {
        float a[RPT][4];
        #pragma unroll
        for (int j = 0; j < RPT; j++) {
            float4 t4 = *(const float4*)(isbase + j * K + k4 * 4);
            a[j][0] = t4.x; a[j][1] = t4.y; a[j][2] = t4.z; a[j][3] = t4.w;
        }
        #pragma unroll
        for (int kk = 0; kk < 4; kk++) {
            float w[CPT];
            const float4* wr = (const float4*)(Ws + (k4 * 4 + kk) * NC + ct * CPT);
            #pragma unroll
            for (int q = 0; q < CPT / 4; q++) {
                float4 w4 = wr[q];
                w[q * 4 + 0] = w4.x; w[q * 4 + 1] = w4.y;
                w[q * 4 + 2] = w4.z; w[q * 4 + 3] = w4.w;
            }
            #pragma unroll
            for (int j = 0; j < RPT; j++)
                #pragma unroll
                for (int c = 0; c < CPT; c++)
                    acc[j][c] = fmaf(a[j][kk], w[c], acc[j][c]);
        }
    }

    if (MODE == 1) {
        float bl[CPT];
        #pragma unroll
        for (int c = 0; c < CPT; c++) bl[c] = __ldg(&p0[ct * CPT + c]);
        #pragma unroll
        for (int j = 0; j < RPT; j++) {
            int gr = row0 + rt * RPT + j;
            if (gr < NN) {
                #pragma unroll
                for (int c = 0; c < CPT; c++) acc[j][c] += bl[c];
                float4* o = (float4*)(g_h1 + (size_t)gr * NC + ct * CPT);
                #pragma unroll
                for (int q = 0; q < CPT / 4; q++)
                    o[q] = make_float4(acc[j][q * 4 + 0], acc[j][q * 4 + 1],
                                       acc[j][q * 4 + 2], acc[j][q * 4 + 3]);
            } else {
                #pragma unroll
                for (int c = 0; c < CPT; c++) acc[j][c] = 0.f;
            }
        }
        __syncthreads();
        float* ssum = Is;
        float* ssq = Is + NC;
        if (tid < 2 * NC) Is[tid] = 0.f;
        __syncthreads();
        #pragma unroll
        for (int c = 0; c < CPT; c++) {
            float sv = 0.f, sq = 0.f;
            #pragma unroll
            for (int j = 0; j < RPT; j++) { sv += acc[j][c]; sq += acc[j][c] * acc[j][c]; }
            atomicAdd(&ssum[ct * CPT + c], sv);
            atomicAdd(&ssq[ct * CPT + c], sq);
        }
        __syncthreads();
        if (tid < NC) {
            atomicAdd(&g_stats[tid], ssum[tid]);
            atomicAdd(&g_stats[128 + tid], ssq[tid]);
        }
    } else {
        uint2* o0 = (MODE == 2) ? g_u2 : g_u3;
        #pragma unroll
        for (int j = 0; j < RPT; j++) {
            int gr = row0 + rt * RPT + j;
            if (gr >= NN) continue;
            float d = __ldg((const float*)&g_dinv[gr]);
            o0[gr * 16 + ct] = make_uint2(pack_h2(acc[j][0] * d, acc[j][1] * d),
                                          pack_h2(acc[j][2] * d, acc[j][3] * d));
        }
    }
}

__global__ void k_final1(const float* __restrict__ g1, const float* __restrict__ be1) {
    int c = threadIdx.x;  // 128
    float mean = g_stats[c] * (1.0f / NN);
    float var = g_stats[128 + c] * (1.0f / NN) - mean * mean;
    float sc = rsqrtf(var + EPS_BN) * __ldg(&g1[c]);
    g_stats[256 + c] = sc;
    g_stats[384 + c] = __ldg(&be1[c]) - mean * sc;
}

// ---------------- launcher ----------------
extern "C" void kernel_launch(void* const* d_in, const int* in_sizes, int n_in,
                              void* d_out, int out_size) {
    const float* x  = (const float*)d_in[0];
    const int* ei   = (const int*)d_in[1];
    const float* W1 = (const float*)d_in[2];
    const float* b1 = (const float*)d_in[3];
    const float* g1 = (const float*)d_in[4];
    const float* be1= (const float*)d_in[5];
    const float* W2 = (const float*)d_in[6];
    const float* b2 = (const float*)d_in[7];
    const float* g2 = (const float*)d_in[8];
    const float* be2= (const float*)d_in[9];
    const float* W3 = (const float*)d_in[10];
    const float* b3 = (const float*)d_in[11];

    const int nE = in_sizes[1] / 2;
    const int* src = ei;
    const int* dst = ei + nE;

    // CSR build + prep
    k_init<<<(NN + 255) / 256, 256>>>();
    k_deg<<<(nE + 255) / 256, 256>>>(dst, nE);
    k_scanprep<<<NBLK, 256>>>(x);
    k_fill<<<(nE + 255) / 256, 256>>>(src, dst, nE);

    // layer 1 (aggregate at 64 ch BEFORE GEMM: A(xW) == (Ax)W)
    k_gather<1><<<NN * 16 / 256, 256>>>(nullptr, nullptr);
    k_gemm<64, 128, 4, 1><<<(NN + 63) / 64, 256>>>(W1, b1, nullptr, nullptr);
    k_final1<<<1, 128>>>(g1, be1);

    // layer 2 (gather fuses BN stats of h2)
    k_gemm<128, 64, 2, 2><<<(NN + 31) / 32, 256>>>(W2, nullptr, nullptr, nullptr);
    k_gather<2><<<NN * 16 / 256, 256>>>(nullptr, b2);

    // layer 3 (gemm inlines final2)
    k_gemm<64, 64, 4, 3><<<(NN + 63) / 64, 256>>>(W3, g2, be2, b2);
    k_gather<3><<<NN * 16 / 256, 256>>>((float*)d_out, b3);
}